// round 1
// baseline (speedup 1.0000x reference)
#include <cuda_runtime.h>

// Problem dims (fixed)
#define BB   1024
#define TT   128
#define DD   128
#define HH   8
#define HDIM 16
#define FFD  512
#define NL   2
#define MM   (BB*TT)          // 131072 tokens

// Scratch (device globals: allocation-free per harness rules)
__device__ float g_qkv[(size_t)MM * 3 * DD];   // also reused for proj outputs [MM,DD]
__device__ float g_tmp[(size_t)MM * FFD];      // attn-out [MM,DD] and FF hidden [MM,FFD]

// ---------------------------------------------------------------------------
// GEMM: C[M,N] = A[M,K] @ W[N,K]^T + bias[N], optional ReLU.
// Tile: BM=128, BN=64, BK=16. 256 threads, each computes 8x4.
// ---------------------------------------------------------------------------
__global__ __launch_bounds__(256) void gemm_bias_kernel(
    const float* __restrict__ A, const float* __restrict__ W,
    const float* __restrict__ bias, float* __restrict__ C,
    int M, int N, int K, int relu)
{
    __shared__ float As[16][128];
    __shared__ float Ws[16][64];
    const int tid = threadIdx.x;
    const int tx = tid & 15, ty = tid >> 4;
    const int bm = blockIdx.y * 128;
    const int bn = blockIdx.x * 64;

    float acc[8][4];
#pragma unroll
    for (int i = 0; i < 8; i++)
#pragma unroll
        for (int j = 0; j < 4; j++) acc[i][j] = 0.f;

    for (int kk = 0; kk < K; kk += 16) {
        // load A tile (128x16) transposed into As[k][m]
#pragma unroll
        for (int i = 0; i < 2; i++) {
            int idx = tid * 2 + i;            // 0..511
            int row = idx >> 2, c4 = idx & 3;
            float4 v = *(const float4*)(A + (size_t)(bm + row) * K + kk + c4 * 4);
            As[c4 * 4 + 0][row] = v.x; As[c4 * 4 + 1][row] = v.y;
            As[c4 * 4 + 2][row] = v.z; As[c4 * 4 + 3][row] = v.w;
        }
        // load W tile (64x16) transposed into Ws[k][n]
        {
            int row = tid >> 2, c4 = tid & 3;
            float4 v = *(const float4*)(W + (size_t)(bn + row) * K + kk + c4 * 4);
            Ws[c4 * 4 + 0][row] = v.x; Ws[c4 * 4 + 1][row] = v.y;
            Ws[c4 * 4 + 2][row] = v.z; Ws[c4 * 4 + 3][row] = v.w;
        }
        __syncthreads();
#pragma unroll
        for (int k = 0; k < 16; k++) {
            float4 a0 = *(const float4*)&As[k][ty * 8];
            float4 a1 = *(const float4*)&As[k][ty * 8 + 4];
            float4 wq = *(const float4*)&Ws[k][tx * 4];
            float a[8] = {a0.x, a0.y, a0.z, a0.w, a1.x, a1.y, a1.z, a1.w};
            float wv[4] = {wq.x, wq.y, wq.z, wq.w};
#pragma unroll
            for (int i = 0; i < 8; i++)
#pragma unroll
                for (int j = 0; j < 4; j++)
                    acc[i][j] = fmaf(a[i], wv[j], acc[i][j]);
        }
        __syncthreads();
    }

#pragma unroll
    for (int i = 0; i < 8; i++) {
        int m = bm + ty * 8 + i;
#pragma unroll
        for (int j = 0; j < 4; j++) {
            int n = bn + tx * 4 + j;
            float v = acc[i][j] + bias[n];
            if (relu) v = fmaxf(v, 0.f);
            C[(size_t)m * N + n] = v;
        }
    }
}

// ---------------------------------------------------------------------------
// Attention: one block per (b,h). 128 threads; thread t owns query row t.
// Online softmax over T=128 keys. K/V tiles + mask in smem.
// ---------------------------------------------------------------------------
__global__ __launch_bounds__(128) void attn_kernel(
    const float* __restrict__ qkv, const float* __restrict__ mask,
    float* __restrict__ out)
{
    const int h = blockIdx.x;
    const int b = blockIdx.y;
    const int t = threadIdx.x;

    __shared__ float ks[TT][HDIM];
    __shared__ float vs[TT][HDIM];
    __shared__ float ms[TT];

    const float* base = qkv + (size_t)b * TT * 3 * DD;
    {
        const float* kr = base + (size_t)t * 3 * DD + DD + h * HDIM;
        const float* vr = kr + DD;
#pragma unroll
        for (int c = 0; c < 4; c++) {
            ((float4*)ks[t])[c] = ((const float4*)kr)[c];
            ((float4*)vs[t])[c] = ((const float4*)vr)[c];
        }
        ms[t] = mask[b * TT + t];
    }
    __syncthreads();

    float q[HDIM];
    const float* qr = base + (size_t)t * 3 * DD + h * HDIM;
#pragma unroll
    for (int c = 0; c < 4; c++) ((float4*)q)[c] = ((const float4*)qr)[c];

    const float scale = 0.25f;  // 1/sqrt(16)
    float m = -1e30f, s = 0.f;
    float o[HDIM];
#pragma unroll
    for (int c = 0; c < HDIM; c++) o[c] = 0.f;

    for (int j = 0; j < TT; j++) {
        float d = 0.f;
#pragma unroll
        for (int c = 0; c < HDIM; c++) d = fmaf(q[c], ks[j][c], d);
        d = d * scale + ms[j];
        float nm = fmaxf(m, d);
        float cor = __expf(m - nm);
        float p = __expf(d - nm);
        s = s * cor + p;
#pragma unroll
        for (int c = 0; c < HDIM; c++) o[c] = fmaf(o[c], cor, p * vs[j][c]);
        m = nm;
    }
    float inv = 1.f / s;
    float* op = out + (size_t)(b * TT + t) * DD + h * HDIM;
#pragma unroll
    for (int c = 0; c < HDIM; c++) op[c] = o[c] * inv;
}

// ---------------------------------------------------------------------------
// Residual + LayerNorm: x[row,:] = LN(x[row,:] + r[row,:]) * g + b (in place)
// one block per token row, 128 threads
// ---------------------------------------------------------------------------
__global__ __launch_bounds__(128) void ln_kernel(
    float* __restrict__ x, const float* __restrict__ r,
    const float* __restrict__ g, const float* __restrict__ bta)
{
    const int row = blockIdx.x;
    const int d = threadIdx.x;
    float t = x[(size_t)row * DD + d] + r[(size_t)row * DD + d];

    float s = t, s2 = t * t;
#pragma unroll
    for (int off = 16; off > 0; off >>= 1) {
        s  += __shfl_down_sync(0xffffffffu, s, off);
        s2 += __shfl_down_sync(0xffffffffu, s2, off);
    }
    __shared__ float ss[4], ss2[4];
    int w = d >> 5, lane = d & 31;
    if (lane == 0) { ss[w] = s; ss2[w] = s2; }
    __syncthreads();
    float sum  = ss[0] + ss[1] + ss[2] + ss[3];
    float sum2 = ss2[0] + ss2[1] + ss2[2] + ss2[3];
    float mean = sum * (1.f / DD);
    float var  = sum2 * (1.f / DD) - mean * mean;
    float y = (t - mean) * rsqrtf(var + 1e-5f) * g[d] + bta[d];
    x[(size_t)row * DD + d] = y;
}

// ---------------------------------------------------------------------------
extern "C" void kernel_launch(void* const* d_in, const int* in_sizes, int n_in,
                              void* d_out, int out_size)
{
    const float* x_in      = (const float*)d_in[0];
    const float* mask      = (const float*)d_in[1];
    const float* in_proj_w = (const float*)d_in[2];
    const float* in_proj_b = (const float*)d_in[3];
    const float* out_w     = (const float*)d_in[4];
    const float* out_b     = (const float*)d_in[5];
    const float* ln1_g     = (const float*)d_in[6];
    const float* ln1_b     = (const float*)d_in[7];
    const float* ff1_w     = (const float*)d_in[8];
    const float* ff1_b     = (const float*)d_in[9];
    const float* ff2_w     = (const float*)d_in[10];
    const float* ff2_b     = (const float*)d_in[11];
    const float* ln2_g     = (const float*)d_in[12];
    const float* ln2_b     = (const float*)d_in[13];
    float* x = (float*)d_out;

    float *qkv, *tmp;
    cudaGetSymbolAddress((void**)&qkv, g_qkv);
    cudaGetSymbolAddress((void**)&tmp, g_tmp);

    // x := input
    cudaMemcpyAsync(x, x_in, sizeof(float) * (size_t)MM * DD,
                    cudaMemcpyDeviceToDevice);

    const dim3 gB(256);
    for (int l = 0; l < NL; l++) {
        // qkv = x @ Wqkv^T + b        [MM, 384]
        gemm_bias_kernel<<<dim3(3 * DD / 64, MM / 128), gB>>>(
            x, in_proj_w + (size_t)l * 3 * DD * DD, in_proj_b + (size_t)l * 3 * DD,
            qkv, MM, 3 * DD, DD, 0);
        // attention -> tmp [MM, DD]
        attn_kernel<<<dim3(HH, BB), 128>>>(qkv, mask, tmp);
        // o = tmp @ out_w^T + out_b -> qkv (reuse)  [MM, DD]
        gemm_bias_kernel<<<dim3(DD / 64, MM / 128), gB>>>(
            tmp, out_w + (size_t)l * DD * DD, out_b + (size_t)l * DD,
            qkv, MM, DD, DD, 0);
        // x = LN(x + o)
        ln_kernel<<<MM, 128>>>(x, qkv, ln1_g + (size_t)l * DD, ln1_b + (size_t)l * DD);
        // h = relu(x @ ff1_w^T + b) -> tmp [MM, FFD]
        gemm_bias_kernel<<<dim3(FFD / 64, MM / 128), gB>>>(
            x, ff1_w + (size_t)l * FFD * DD, ff1_b + (size_t)l * FFD,
            tmp, MM, FFD, DD, 1);
        // f = h @ ff2_w^T + b -> qkv [MM, DD]
        gemm_bias_kernel<<<dim3(DD / 64, MM / 128), gB>>>(
            tmp, ff2_w + (size_t)l * DD * FFD, ff2_b + (size_t)l * DD,
            qkv, MM, DD, FFD, 0);
        // x = LN(x + f)
        ln_kernel<<<MM, 128>>>(x, qkv, ln2_g + (size_t)l * DD, ln2_b + (size_t)l * DD);
    }
}

// round 2
// speedup vs baseline: 1.3868x; 1.3868x over previous
#include <cuda_runtime.h>
#include <mma.h>
using namespace nvcuda;

// Problem dims (fixed)
#define BB   1024
#define TT   128
#define DD   128
#define HH   8
#define HDIM 16
#define FFD  512
#define NL   2
#define MM   (BB*TT)          // 131072 tokens

// Scratch (device globals: allocation-free per harness rules)
__device__ float g_qkv[(size_t)MM * 3 * DD];
__device__ float g_tmp[(size_t)MM * FFD];

// ---------------------------------------------------------------------------
// Fast exp: exp2-based, FFMA-only (avoids the MUFU throughput wall).
// Accurate to ~2.4e-6 rel over the used range. Clamps at -80 (underflow->~0).
// ---------------------------------------------------------------------------
__device__ __forceinline__ float fast_exp(float x) {
    x = fmaxf(x, -80.f);
    float t  = x * 1.4426950408889634f;       // x * log2(e)
    float fn = t + 12582912.f;                // round-to-nearest via 1.5*2^23
    int   ni = __float_as_int(fn) - 0x4B400000;
    float r  = t - (fn - 12582912.f);         // r in [-0.5, 0.5]
    float p  = 0.00133336f;                   // 2^r Taylor (ln2 powers)
    p = fmaf(p, r, 0.00961813f);
    p = fmaf(p, r, 0.05550411f);
    p = fmaf(p, r, 0.24022651f);
    p = fmaf(p, r, 0.69314718f);
    p = fmaf(p, r, 1.0f);
    return p * __int_as_float((ni + 127) << 23);
}

// ---------------------------------------------------------------------------
// TF32 tensor-core GEMM: C[M,N] = A[M,K] @ W[N,K]^T + bias, optional ReLU.
// Tile BM=128, BN=64, BK=16; 8 warps, each warp 32x32 via 2x2 wmma m16n16k8.
// W is [N,K] row-major == B[K,N] col-major with ld=K, so matrix_b loads col_major.
// ---------------------------------------------------------------------------
#define BM  128
#define BN  64
#define BK  16
#define LDA 20     // padded smem ld (multiple of 4 for wmma)

__global__ __launch_bounds__(256) void gemm_tf32(
    const float* __restrict__ A, const float* __restrict__ W,
    const float* __restrict__ bias, float* __restrict__ C,
    int M, int N, int K, int relu)
{
    __shared__ float sm[BM * BN];              // 32KB: tiles alias front, staging uses all
    float* As = sm;                            // [BM][LDA]
    float* Ws = sm + BM * LDA;                 // [BN][LDA]

    const int tid = threadIdx.x;
    const int wid = tid >> 5;
    const int wm  = wid & 3;                   // warp row (32 rows each)
    const int wn  = wid >> 2;                  // warp col (32 cols each)
    const size_t bm = (size_t)blockIdx.y * BM;
    const size_t bn = (size_t)blockIdx.x * BN;

    wmma::fragment<wmma::accumulator, 16, 16, 8, float> acc[2][2];
#pragma unroll
    for (int i = 0; i < 2; i++)
#pragma unroll
        for (int j = 0; j < 2; j++) wmma::fill_fragment(acc[i][j], 0.f);

    for (int kk = 0; kk < K; kk += BK) {
        // A tile: 128x16
#pragma unroll
        for (int i = 0; i < 2; i++) {
            int f4  = tid + i * 256;           // 0..511
            int row = f4 >> 2;
            int c   = (f4 & 3) * 4;
            float4 v = *(const float4*)(A + (bm + row) * K + kk + c);
            float* p = As + row * LDA + c;
            p[0] = wmma::__float_to_tf32(v.x);
            p[1] = wmma::__float_to_tf32(v.y);
            p[2] = wmma::__float_to_tf32(v.z);
            p[3] = wmma::__float_to_tf32(v.w);
        }
        // W tile: 64x16
        {
            int row = tid >> 2;
            int c   = (tid & 3) * 4;
            float4 v = *(const float4*)(W + (bn + row) * K + kk + c);
            float* p = Ws + row * LDA + c;
            p[0] = wmma::__float_to_tf32(v.x);
            p[1] = wmma::__float_to_tf32(v.y);
            p[2] = wmma::__float_to_tf32(v.z);
            p[3] = wmma::__float_to_tf32(v.w);
        }
        __syncthreads();

#pragma unroll
        for (int ks = 0; ks < BK; ks += 8) {
            wmma::fragment<wmma::matrix_a, 16, 16, 8, wmma::precision::tf32, wmma::row_major> a[2];
            wmma::fragment<wmma::matrix_b, 16, 16, 8, wmma::precision::tf32, wmma::col_major> b[2];
            wmma::load_matrix_sync(a[0], As + (wm * 32)      * LDA + ks, LDA);
            wmma::load_matrix_sync(a[1], As + (wm * 32 + 16) * LDA + ks, LDA);
            wmma::load_matrix_sync(b[0], Ws + (wn * 32)      * LDA + ks, LDA);
            wmma::load_matrix_sync(b[1], Ws + (wn * 32 + 16) * LDA + ks, LDA);
#pragma unroll
            for (int i = 0; i < 2; i++)
#pragma unroll
                for (int j = 0; j < 2; j++)
                    wmma::mma_sync(acc[i][j], a[i], b[j], acc[i][j]);
        }
        __syncthreads();
    }

    // Epilogue: stage accumulators in smem, then biased/ReLU float4 writes.
#pragma unroll
    for (int i = 0; i < 2; i++)
#pragma unroll
        for (int j = 0; j < 2; j++)
            wmma::store_matrix_sync(sm + (wm * 32 + 16 * i) * BN + wn * 32 + 16 * j,
                                    acc[i][j], BN, wmma::mem_row_major);
    __syncthreads();

#pragma unroll
    for (int t = 0; t < 8; t++) {
        int idx = tid + t * 256;               // 0..2047 float4s
        int row = idx >> 4;
        int c   = (idx & 15) * 4;
        float4 v  = *(float4*)(sm + row * BN + c);
        float4 bz = *(const float4*)(bias + bn + c);
        v.x += bz.x; v.y += bz.y; v.z += bz.z; v.w += bz.w;
        if (relu) {
            v.x = fmaxf(v.x, 0.f); v.y = fmaxf(v.y, 0.f);
            v.z = fmaxf(v.z, 0.f); v.w = fmaxf(v.w, 0.f);
        }
        *(float4*)(C + (bm + row) * N + bn + c) = v;
    }
}

// ---------------------------------------------------------------------------
// Attention: one block per (b,h). 128 threads; thread t owns query row t.
// Single pass, no max subtraction (scores bounded; masked -> exp underflow).
// ---------------------------------------------------------------------------
__global__ __launch_bounds__(128) void attn_kernel(
    const float* __restrict__ qkv, const float* __restrict__ mask,
    float* __restrict__ out)
{
    const int h = blockIdx.x;
    const int b = blockIdx.y;
    const int t = threadIdx.x;

    __shared__ float ks[TT][HDIM];
    __shared__ float vs[TT][HDIM];
    __shared__ float ms[TT];

    const float* base = qkv + (size_t)b * TT * 3 * DD;
    {
        const float* kr = base + (size_t)t * 3 * DD + DD + h * HDIM;
        const float* vr = kr + DD;
#pragma unroll
        for (int c = 0; c < 4; c++) {
            ((float4*)ks[t])[c] = ((const float4*)kr)[c];
            ((float4*)vs[t])[c] = ((const float4*)vr)[c];
        }
        ms[t] = mask[b * TT + t];
    }
    __syncthreads();

    float q[HDIM];
    const float* qr = base + (size_t)t * 3 * DD + h * HDIM;
#pragma unroll
    for (int c = 0; c < 4; c++) ((float4*)q)[c] = ((const float4*)qr)[c];

    const float scale = 0.25f;  // 1/sqrt(16)
    float s = 0.f;
    float o[HDIM];
#pragma unroll
    for (int c = 0; c < HDIM; c++) o[c] = 0.f;

    for (int j = 0; j < TT; j++) {
        float d = 0.f;
#pragma unroll
        for (int c = 0; c < HDIM; c++) d = fmaf(q[c], ks[j][c], d);
        float p = fast_exp(fmaf(d, scale, ms[j]));
        s += p;
#pragma unroll
        for (int c = 0; c < HDIM; c++) o[c] = fmaf(p, vs[j][c], o[c]);
    }
    float inv = 1.f / s;
    float* op = out + (size_t)(b * TT + t) * DD + h * HDIM;
#pragma unroll
    for (int c = 0; c < HDIM; c++) op[c] = o[c] * inv;
}

// ---------------------------------------------------------------------------
// Residual + LayerNorm, warp-per-row (no smem, no block sync), float4 I/O.
// 256 threads = 8 rows per block.
// ---------------------------------------------------------------------------
__global__ __launch_bounds__(256) void ln_kernel(
    float* __restrict__ x, const float* __restrict__ r,
    const float* __restrict__ g, const float* __restrict__ bta)
{
    const int row  = blockIdx.x * 8 + (threadIdx.x >> 5);
    const int lane = threadIdx.x & 31;
    const size_t off = (size_t)row * DD + lane * 4;

    float4 xv = *(const float4*)(x + off);
    float4 rv = *(const float4*)(r + off);
    float4 t;
    t.x = xv.x + rv.x; t.y = xv.y + rv.y; t.z = xv.z + rv.z; t.w = xv.w + rv.w;

    float s  = t.x + t.y + t.z + t.w;
    float s2 = t.x * t.x + t.y * t.y + t.z * t.z + t.w * t.w;
#pragma unroll
    for (int o = 16; o > 0; o >>= 1) {
        s  += __shfl_xor_sync(0xffffffffu, s,  o);
        s2 += __shfl_xor_sync(0xffffffffu, s2, o);
    }
    float mean = s * (1.f / DD);
    float var  = s2 * (1.f / DD) - mean * mean;
    float rstd = rsqrtf(var + 1e-5f);

    float4 gv = *(const float4*)(g   + lane * 4);
    float4 bv = *(const float4*)(bta + lane * 4);
    float4 y;
    y.x = (t.x - mean) * rstd * gv.x + bv.x;
    y.y = (t.y - mean) * rstd * gv.y + bv.y;
    y.z = (t.z - mean) * rstd * gv.z + bv.z;
    y.w = (t.w - mean) * rstd * gv.w + bv.w;
    *(float4*)(x + off) = y;
}

// ---------------------------------------------------------------------------
extern "C" void kernel_launch(void* const* d_in, const int* in_sizes, int n_in,
                              void* d_out, int out_size)
{
    const float* x_in      = (const float*)d_in[0];
    const float* mask      = (const float*)d_in[1];
    const float* in_proj_w = (const float*)d_in[2];
    const float* in_proj_b = (const float*)d_in[3];
    const float* out_w     = (const float*)d_in[4];
    const float* out_b     = (const float*)d_in[5];
    const float* ln1_g     = (const float*)d_in[6];
    const float* ln1_b     = (const float*)d_in[7];
    const float* ff1_w     = (const float*)d_in[8];
    const float* ff1_b     = (const float*)d_in[9];
    const float* ff2_w     = (const float*)d_in[10];
    const float* ff2_b     = (const float*)d_in[11];
    const float* ln2_g     = (const float*)d_in[12];
    const float* ln2_b     = (const float*)d_in[13];
    float* x = (float*)d_out;

    float *qkv, *tmp;
    cudaGetSymbolAddress((void**)&qkv, g_qkv);
    cudaGetSymbolAddress((void**)&tmp, g_tmp);

    cudaMemcpyAsync(x, x_in, sizeof(float) * (size_t)MM * DD,
                    cudaMemcpyDeviceToDevice);

    const dim3 gB(256);
    for (int l = 0; l < NL; l++) {
        // qkv = x @ Wqkv^T + b   [MM, 384]
        gemm_tf32<<<dim3(3 * DD / BN, MM / BM), gB>>>(
            x, in_proj_w + (size_t)l * 3 * DD * DD, in_proj_b + (size_t)l * 3 * DD,
            qkv, MM, 3 * DD, DD, 0);
        // attention -> tmp [MM, DD]
        attn_kernel<<<dim3(HH, BB), 128>>>(qkv, mask, tmp);
        // o = tmp @ out_w^T + out_b -> qkv  [MM, DD]
        gemm_tf32<<<dim3(DD / BN, MM / BM), gB>>>(
            tmp, out_w + (size_t)l * DD * DD, out_b + (size_t)l * DD,
            qkv, MM, DD, DD, 0);
        // x = LN(x + o)
        ln_kernel<<<MM / 8, 256>>>(x, qkv, ln1_g + (size_t)l * DD, ln1_b + (size_t)l * DD);
        // h = relu(x @ ff1_w^T + b) -> tmp [MM, FFD]
        gemm_tf32<<<dim3(FFD / BN, MM / BM), gB>>>(
            x, ff1_w + (size_t)l * FFD * DD, ff1_b + (size_t)l * FFD,
            tmp, MM, FFD, DD, 1);
        // f = h @ ff2_w^T + b -> qkv [MM, DD]
        gemm_tf32<<<dim3(DD / BN, MM / BM), gB>>>(
            tmp, ff2_w + (size_t)l * DD * FFD, ff2_b + (size_t)l * DD,
            qkv, MM, DD, FFD, 0);
        // x = LN(x + f)
        ln_kernel<<<MM / 8, 256>>>(x, qkv, ln2_g + (size_t)l * DD, ln2_b + (size_t)l * DD);
    }
}

// round 4
// speedup vs baseline: 1.4420x; 1.0398x over previous
#include <cuda_runtime.h>
#include <mma.h>
#include <cstdint>
using namespace nvcuda;

// Problem dims (fixed)
#define BB   1024
#define TT   128
#define DD   128
#define HH   8
#define HDIM 16
#define FFD  512
#define NL   2
#define MM   (BB*TT)          // 131072 tokens

// Scratch (device globals: allocation-free per harness rules)
__device__ float g_qkv[(size_t)MM * 3 * DD];
__device__ float g_tmp[(size_t)MM * FFD];

__device__ __forceinline__ float to_tf32(float x) {
    float r;
    asm("cvt.rna.tf32.f32 %0, %1;" : "=f"(r) : "f"(x));
    return r;
}

// ---------------------------------------------------------------------------
// TF32 tensor GEMM: C[M,N] = A[M,K] @ W[N,K]^T + bias.
// mode 0: plain   mode 1: ReLU   mode 2: fused residual+LayerNorm (N==128):
//         C (=x) <- LN(C_old + gemm + bias) * gamma + beta
// Tile 128x128, BK=32, 2-stage double buffer, single sync per K-tile.
// 8 warps, warp tile 64x32 (4x2 wmma m16n16k8 tf32 frags).
// ---------------------------------------------------------------------------
#define TLD   36                         // smem tile ld (32+4 pad)
#define TILE_F (128*TLD)                 // 4608 floats per tile
#define STG_F  (2*TILE_F)                // A+B per stage
#define CLD   132                        // epilogue staging ld
#define SMEM_DYN (2*STG_F*4)             // 73728 bytes

__global__ __launch_bounds__(256) void gemm_tc(
    const float* __restrict__ A, const float* __restrict__ W,
    const float* __restrict__ bias, float* __restrict__ C,
    const float* __restrict__ gamma, const float* __restrict__ beta,
    int N, int K, int mode)
{
    extern __shared__ float sm[];
    const int tid  = threadIdx.x;
    const int wid  = tid >> 5;
    const int lane = tid & 31;
    const int wm   = wid & 1;            // warp row: 64 rows
    const int wn   = wid >> 1;           // warp col: 32 cols
    const size_t bm = (size_t)blockIdx.y * 128;
    const size_t bn = (size_t)blockIdx.x * 128;

    const int r0 = tid >> 3;             // 0..31 (row within 32-row group)
    const int c4 = tid & 7;              // float4 column (k)

    wmma::fragment<wmma::accumulator, 16, 16, 8, float> acc[4][2];
#pragma unroll
    for (int i = 0; i < 4; i++)
#pragma unroll
        for (int j = 0; j < 2; j++) wmma::fill_fragment(acc[i][j], 0.f);

    const int NT = K >> 5;
    const float* Ap = A + (bm + r0) * K + c4 * 4;
    const float* Wp = W + (bn + r0) * K + c4 * 4;
    const int sts_off = r0 * TLD + c4 * 4;

    float4 ra[4], rw[4];
    // prologue: load + store stage 0
#pragma unroll
    for (int i = 0; i < 4; i++) {
        ra[i] = *(const float4*)(Ap + (size_t)i * 32 * K);
        rw[i] = *(const float4*)(Wp + (size_t)i * 32 * K);
    }
    {
        float* As = sm;
        float* Ws = sm + TILE_F;
#pragma unroll
        for (int i = 0; i < 4; i++) {
            float* pa = As + i * 32 * TLD + sts_off;
            pa[0] = to_tf32(ra[i].x); pa[1] = to_tf32(ra[i].y);
            pa[2] = to_tf32(ra[i].z); pa[3] = to_tf32(ra[i].w);
            float* pw = Ws + i * 32 * TLD + sts_off;
            pw[0] = to_tf32(rw[i].x); pw[1] = to_tf32(rw[i].y);
            pw[2] = to_tf32(rw[i].z); pw[3] = to_tf32(rw[i].w);
        }
    }
    __syncthreads();

    for (int t = 0; t < NT; t++) {
        if (t + 1 < NT) {
            const int kk = (t + 1) * 32;
#pragma unroll
            for (int i = 0; i < 4; i++) {
                ra[i] = *(const float4*)(Ap + (size_t)i * 32 * K + kk);
                rw[i] = *(const float4*)(Wp + (size_t)i * 32 * K + kk);
            }
        }
        // compute on stage t&1
        {
            float* As = sm + (t & 1) * STG_F;
            float* Ws = As + TILE_F;
#pragma unroll
            for (int ks = 0; ks < 4; ks++) {
                wmma::fragment<wmma::matrix_a, 16, 16, 8, wmma::precision::tf32, wmma::row_major> af[4];
                wmma::fragment<wmma::matrix_b, 16, 16, 8, wmma::precision::tf32, wmma::col_major> bf[2];
#pragma unroll
                for (int i = 0; i < 4; i++)
                    wmma::load_matrix_sync(af[i], As + (wm * 64 + i * 16) * TLD + ks * 8, TLD);
#pragma unroll
                for (int j = 0; j < 2; j++)
                    wmma::load_matrix_sync(bf[j], Ws + (wn * 32 + j * 16) * TLD + ks * 8, TLD);
#pragma unroll
                for (int i = 0; i < 4; i++)
#pragma unroll
                    for (int j = 0; j < 2; j++)
                        wmma::mma_sync(acc[i][j], af[i], bf[j], acc[i][j]);
            }
        }
        // store stage t+1 (other buffer; safe to overlap with compute readers)
        if (t + 1 < NT) {
            float* As = sm + ((t + 1) & 1) * STG_F;
            float* Ws = As + TILE_F;
#pragma unroll
            for (int i = 0; i < 4; i++) {
                float* pa = As + i * 32 * TLD + sts_off;
                pa[0] = to_tf32(ra[i].x); pa[1] = to_tf32(ra[i].y);
                pa[2] = to_tf32(ra[i].z); pa[3] = to_tf32(ra[i].w);
                float* pw = Ws + i * 32 * TLD + sts_off;
                pw[0] = to_tf32(rw[i].x); pw[1] = to_tf32(rw[i].y);
                pw[2] = to_tf32(rw[i].z); pw[3] = to_tf32(rw[i].w);
            }
        }
        __syncthreads();
    }

    // Epilogue: stage accumulators in smem (aliases pipeline buffers)
#pragma unroll
    for (int i = 0; i < 4; i++)
#pragma unroll
        for (int j = 0; j < 2; j++)
            wmma::store_matrix_sync(sm + (wm * 64 + i * 16) * CLD + wn * 32 + j * 16,
                                    acc[i][j], CLD, wmma::mem_row_major);
    __syncthreads();

    if (mode == 2) {
        // fused residual + LayerNorm (N==128, bn==0); warp per row, 16 rows/warp
        float4 gv = *(const float4*)(gamma + lane * 4);
        float4 bv = *(const float4*)(beta  + lane * 4);
        float4 bz = *(const float4*)(bias  + lane * 4);
#pragma unroll
        for (int i = 0; i < 16; i++) {
            const int row = wid * 16 + i;
            float4 v = *(float4*)(sm + row * CLD + lane * 4);
            const size_t off = (bm + row) * DD + lane * 4;
            float4 xv = *(const float4*)(C + off);
            float4 tvec;
            tvec.x = v.x + bz.x + xv.x;
            tvec.y = v.y + bz.y + xv.y;
            tvec.z = v.z + bz.z + xv.z;
            tvec.w = v.w + bz.w + xv.w;
            float s  = tvec.x + tvec.y + tvec.z + tvec.w;
            float s2 = tvec.x * tvec.x + tvec.y * tvec.y
                     + tvec.z * tvec.z + tvec.w * tvec.w;
#pragma unroll
            for (int o = 16; o > 0; o >>= 1) {
                s  += __shfl_xor_sync(0xffffffffu, s,  o);
                s2 += __shfl_xor_sync(0xffffffffu, s2, o);
            }
            float mean = s * (1.f / DD);
            float var  = s2 * (1.f / DD) - mean * mean;
            float rstd = rsqrtf(var + 1e-5f);
            float4 y;
            y.x = (tvec.x - mean) * rstd * gv.x + bv.x;
            y.y = (tvec.y - mean) * rstd * gv.y + bv.y;
            y.z = (tvec.z - mean) * rstd * gv.z + bv.z;
            y.w = (tvec.w - mean) * rstd * gv.w + bv.w;
            *(float4*)(C + off) = y;
        }
    } else {
        // bias (+ReLU) writes: 4096 float4s, 16 per thread
#pragma unroll
        for (int i = 0; i < 16; i++) {
            int idx = i * 256 + tid;
            int row = idx >> 5;
            int cc  = (idx & 31) * 4;
            float4 v  = *(float4*)(sm + row * CLD + cc);
            float4 bz = *(const float4*)(bias + bn + cc);
            v.x += bz.x; v.y += bz.y; v.z += bz.z; v.w += bz.w;
            if (mode == 1) {
                v.x = fmaxf(v.x, 0.f); v.y = fmaxf(v.y, 0.f);
                v.z = fmaxf(v.z, 0.f); v.w = fmaxf(v.w, 0.f);
            }
            *(float4*)(C + (bm + row) * N + bn + cc) = v;
        }
    }
}

// ---------------------------------------------------------------------------
// Fast exp (FFMA-only; avoids MUFU throughput wall)
// ---------------------------------------------------------------------------
__device__ __forceinline__ float fast_exp(float x) {
    x = fmaxf(x, -80.f);
    float t  = x * 1.4426950408889634f;
    float fn = t + 12582912.f;
    int   ni = __float_as_int(fn) - 0x4B400000;
    float r  = t - (fn - 12582912.f);
    float p  = 0.00133336f;
    p = fmaf(p, r, 0.00961813f);
    p = fmaf(p, r, 0.05550411f);
    p = fmaf(p, r, 0.24022651f);
    p = fmaf(p, r, 0.69314718f);
    p = fmaf(p, r, 1.0f);
    return p * __int_as_float((ni + 127) << 23);
}

// ---------------------------------------------------------------------------
// Attention: one block per (b,h), thread t owns query row t, single pass.
// ---------------------------------------------------------------------------
__global__ __launch_bounds__(128) void attn_kernel(
    const float* __restrict__ qkv, const float* __restrict__ mask,
    float* __restrict__ out)
{
    const int h = blockIdx.x;
    const int b = blockIdx.y;
    const int t = threadIdx.x;

    __shared__ float ks[TT][HDIM];
    __shared__ float vs[TT][HDIM];
    __shared__ float ms[TT];

    const float* base = qkv + (size_t)b * TT * 3 * DD;
    {
        const float* kr = base + (size_t)t * 3 * DD + DD + h * HDIM;
        const float* vr = kr + DD;
#pragma unroll
        for (int c = 0; c < 4; c++) {
            ((float4*)ks[t])[c] = ((const float4*)kr)[c];
            ((float4*)vs[t])[c] = ((const float4*)vr)[c];
        }
        ms[t] = mask[b * TT + t];
    }
    __syncthreads();

    float q[HDIM];
    const float* qr = base + (size_t)t * 3 * DD + h * HDIM;
#pragma unroll
    for (int c = 0; c < 4; c++) ((float4*)q)[c] = ((const float4*)qr)[c];

    const float scale = 0.25f;
    float s = 0.f;
    float o[HDIM];
#pragma unroll
    for (int c = 0; c < HDIM; c++) o[c] = 0.f;

    for (int j = 0; j < TT; j++) {
        float d = 0.f;
#pragma unroll
        for (int c = 0; c < HDIM; c++) d = fmaf(q[c], ks[j][c], d);
        float p = fast_exp(fmaf(d, scale, ms[j]));
        s += p;
#pragma unroll
        for (int c = 0; c < HDIM; c++) o[c] = fmaf(p, vs[j][c], o[c]);
    }
    float inv = 1.f / s;
    float* op = out + (size_t)(b * TT + t) * DD + h * HDIM;
#pragma unroll
    for (int c = 0; c < HDIM; c++) op[c] = o[c] * inv;
}

// ---------------------------------------------------------------------------
extern "C" void kernel_launch(void* const* d_in, const int* in_sizes, int n_in,
                              void* d_out, int out_size)
{
    const float* x_in      = (const float*)d_in[0];
    const float* mask      = (const float*)d_in[1];
    const float* in_proj_w = (const float*)d_in[2];
    const float* in_proj_b = (const float*)d_in[3];
    const float* out_w     = (const float*)d_in[4];
    const float* out_b     = (const float*)d_in[5];
    const float* ln1_g     = (const float*)d_in[6];
    const float* ln1_b     = (const float*)d_in[7];
    const float* ff1_w     = (const float*)d_in[8];
    const float* ff1_b     = (const float*)d_in[9];
    const float* ff2_w     = (const float*)d_in[10];
    const float* ff2_b     = (const float*)d_in[11];
    const float* ln2_g     = (const float*)d_in[12];
    const float* ln2_b     = (const float*)d_in[13];
    float* x = (float*)d_out;

    float *qkv, *tmp;
    cudaGetSymbolAddress((void**)&qkv, g_qkv);
    cudaGetSymbolAddress((void**)&tmp, g_tmp);

    cudaFuncSetAttribute(gemm_tc, cudaFuncAttributeMaxDynamicSharedMemorySize, SMEM_DYN);

    cudaMemcpyAsync(x, x_in, sizeof(float) * (size_t)MM * DD,
                    cudaMemcpyDeviceToDevice);

    for (int l = 0; l < NL; l++) {
        // qkv = x @ Wqkv^T + b   [MM, 384]
        gemm_tc<<<dim3(3, MM / 128), 256, SMEM_DYN>>>(
            x, in_proj_w + (size_t)l * 3 * DD * DD, in_proj_b + (size_t)l * 3 * DD,
            qkv, nullptr, nullptr, 3 * DD, DD, 0);
        // attention -> tmp [MM, DD]
        attn_kernel<<<dim3(HH, BB), 128>>>(qkv, mask, tmp);
        // x = LN(x + tmp @ out_w^T + out_b)   (fused epilogue)
        gemm_tc<<<dim3(1, MM / 128), 256, SMEM_DYN>>>(
            tmp, out_w + (size_t)l * DD * DD, out_b + (size_t)l * DD,
            x, ln1_g + (size_t)l * DD, ln1_b + (size_t)l * DD, DD, DD, 2);
        // h = relu(x @ ff1_w^T + b) -> tmp [MM, FFD]
        gemm_tc<<<dim3(4, MM / 128), 256, SMEM_DYN>>>(
            x, ff1_w + (size_t)l * FFD * DD, ff1_b + (size_t)l * FFD,
            tmp, nullptr, nullptr, FFD, DD, 1);
        // x = LN(x + tmp @ ff2_w^T + b)   (fused epilogue)
        gemm_tc<<<dim3(1, MM / 128), 256, SMEM_DYN>>>(
            tmp, ff2_w + (size_t)l * DD * FFD, ff2_b + (size_t)l * DD,
            x, ln2_g + (size_t)l * DD, ln2_b + (size_t)l * DD, DD, FFD, 2);
    }
}

// round 5
// speedup vs baseline: 2.7224x; 1.8879x over previous
#include <cuda_runtime.h>
#include <cuda_fp16.h>
#include <mma.h>
#include <cstdint>
using namespace nvcuda;

// Problem dims (fixed)
#define BB   1024
#define TT   128
#define DD   128
#define HH   8
#define HDIM 16
#define FFD  512
#define NL   2
#define MM   (BB*TT)          // 131072 tokens

// fp16 scratch (device globals: allocation-free per harness rules)
__device__ __half g_wqkv[(size_t)NL * 3 * DD * DD];
__device__ __half g_wout[(size_t)NL * DD * DD];
__device__ __half g_wff1[(size_t)NL * FFD * DD];
__device__ __half g_wff2[(size_t)NL * DD * FFD];
__device__ __half g_xh  [(size_t)MM * DD];        // fp16 mirror of x
__device__ __half g_qkvh[(size_t)MM * 3 * DD];
__device__ __half g_attnh[(size_t)MM * DD];
__device__ __half g_hh  [(size_t)MM * FFD];

// ---------------------------------------------------------------------------
// f32 -> f16 convert (grid-stride, 4 elems/thread)
// ---------------------------------------------------------------------------
__global__ void cvt_f2h(const float* __restrict__ src, __half* __restrict__ dst, int n4) {
    int i = blockIdx.x * blockDim.x + threadIdx.x;
    if (i < n4) {
        float4 v = ((const float4*)src)[i];
        __half2 h0 = __floats2half2_rn(v.x, v.y);
        __half2 h1 = __floats2half2_rn(v.z, v.w);
        uint2 u;
        u.x = *reinterpret_cast<uint32_t*>(&h0);
        u.y = *reinterpret_cast<uint32_t*>(&h1);
        ((uint2*)dst)[i] = u;
    }
}

// ---------------------------------------------------------------------------
// fp16 tensor GEMM: C[M,N] = A[M,K] @ W[N,K]^T + bias.
// mode 0: fp16 out   mode 1: ReLU fp16 out
// mode 2: fused residual+LN (N==128): X <- LN(X + gemm + bias)*gamma+beta,
//         also writes fp16 mirror Xh.
// Tile 128x128, BK=32, 4-stage cp.async pipeline, 256 threads,
// 8 warps each 64x32 (4x2 wmma m16n16k16).
// ---------------------------------------------------------------------------
#define BK   32
#define ALD  40                          // halves per smem row (32+8 pad)
#define STG_B 20480                      // bytes/stage: (128*40)*2 halves * 2
#define NS   4
#define CLD  132
#define SMEM_DYN (NS*STG_B)              // 81920 B

__device__ __forceinline__ uint32_t smem_u32(const void* p) {
    uint32_t a;
    asm("{ .reg .u64 t; cvta.to.shared.u64 t, %1; cvt.u32.u64 %0, t; }"
        : "=r"(a) : "l"(p));
    return a;
}
__device__ __forceinline__ void cp16(uint32_t dst, const void* src) {
    asm volatile("cp.async.ca.shared.global [%0], [%1], 16;" :: "r"(dst), "l"(src));
}

__global__ __launch_bounds__(256) void gemm_h(
    const __half* __restrict__ A, const __half* __restrict__ W,
    const float* __restrict__ bias,
    __half* __restrict__ Ch,                       // modes 0/1
    float* __restrict__ X, __half* __restrict__ Xh,// mode 2
    const float* __restrict__ gamma, const float* __restrict__ beta,
    int N, int K, int mode)
{
    extern __shared__ __align__(16) char smem[];
    const uint32_t sbase = smem_u32(smem);
    const int tid  = threadIdx.x;
    const int wid  = tid >> 5;
    const int lane = tid & 31;
    const int wm   = wid & 1;
    const int wn   = wid >> 1;
    const size_t bm = (size_t)blockIdx.y * 128;
    const size_t bn = (size_t)blockIdx.x * 128;
    const int NT = K / BK;

    // chunk mapping for cp.async: 512 chunks of 16B per operand tile
    const int ch0 = tid, ch1 = tid + 256;
    const int rA0 = ch0 >> 2, cA0 = ch0 & 3;
    const int rA1 = ch1 >> 2, cA1 = ch1 & 3;

    wmma::fragment<wmma::accumulator, 16, 16, 16, float> acc[4][2];
#pragma unroll
    for (int i = 0; i < 4; i++)
#pragma unroll
        for (int j = 0; j < 2; j++) wmma::fill_fragment(acc[i][j], 0.f);

    // prologue: issue NS-1 stages
#pragma unroll
    for (int t = 0; t < NS - 1; t++) {
        if (t < NT) {
            const int kk = t * BK;
            const uint32_t sb = sbase + (t % NS) * STG_B;
            cp16(sb + (rA0 * ALD + cA0 * 8) * 2, A + (bm + rA0) * K + kk + cA0 * 8);
            cp16(sb + (rA1 * ALD + cA1 * 8) * 2, A + (bm + rA1) * K + kk + cA1 * 8);
            cp16(sb + 10240 + (rA0 * ALD + cA0 * 8) * 2, W + (bn + rA0) * K + kk + cA0 * 8);
            cp16(sb + 10240 + (rA1 * ALD + cA1 * 8) * 2, W + (bn + rA1) * K + kk + cA1 * 8);
        }
        asm volatile("cp.async.commit_group;");
    }

    for (int t = 0; t < NT; t++) {
        asm volatile("cp.async.wait_group %0;" :: "n"(NS - 2));
        __syncthreads();
        // compute tile t
        {
            const __half* As = (const __half*)(smem + (t % NS) * STG_B);
            const __half* Ws = As + 5120;
#pragma unroll
            for (int ks = 0; ks < 2; ks++) {
                wmma::fragment<wmma::matrix_a, 16, 16, 16, __half, wmma::row_major> af[4];
                wmma::fragment<wmma::matrix_b, 16, 16, 16, __half, wmma::col_major> bf[2];
#pragma unroll
                for (int i = 0; i < 4; i++)
                    wmma::load_matrix_sync(af[i], As + (wm * 64 + i * 16) * ALD + ks * 16, ALD);
#pragma unroll
                for (int j = 0; j < 2; j++)
                    wmma::load_matrix_sync(bf[j], Ws + (wn * 32 + j * 16) * ALD + ks * 16, ALD);
#pragma unroll
                for (int i = 0; i < 4; i++)
#pragma unroll
                    for (int j = 0; j < 2; j++)
                        wmma::mma_sync(acc[i][j], af[i], bf[j], acc[i][j]);
            }
        }
        __syncthreads();
        // issue stage t+NS-1
        {
            const int tn = t + NS - 1;
            if (tn < NT) {
                const int kk = tn * BK;
                const uint32_t sb = sbase + (tn % NS) * STG_B;
                cp16(sb + (rA0 * ALD + cA0 * 8) * 2, A + (bm + rA0) * K + kk + cA0 * 8);
                cp16(sb + (rA1 * ALD + cA1 * 8) * 2, A + (bm + rA1) * K + kk + cA1 * 8);
                cp16(sb + 10240 + (rA0 * ALD + cA0 * 8) * 2, W + (bn + rA0) * K + kk + cA0 * 8);
                cp16(sb + 10240 + (rA1 * ALD + cA1 * 8) * 2, W + (bn + rA1) * K + kk + cA1 * 8);
            }
            asm volatile("cp.async.commit_group;");
        }
    }

    // Epilogue: stage f32 accumulators in smem (aliases pipeline buffers)
    float* smf = (float*)smem;
#pragma unroll
    for (int i = 0; i < 4; i++)
#pragma unroll
        for (int j = 0; j < 2; j++)
            wmma::store_matrix_sync(smf + (wm * 64 + i * 16) * CLD + wn * 32 + j * 16,
                                    acc[i][j], CLD, wmma::mem_row_major);
    __syncthreads();

    if (mode == 2) {
        // fused residual + LayerNorm (N==128, bn==0); warp per row, 16 rows/warp
        float4 gv = *(const float4*)(gamma + lane * 4);
        float4 bv = *(const float4*)(beta  + lane * 4);
        float4 bz = *(const float4*)(bias  + lane * 4);
#pragma unroll
        for (int i = 0; i < 16; i++) {
            const int row = wid * 16 + i;
            float4 v = *(float4*)(smf + row * CLD + lane * 4);
            const size_t off = (bm + row) * DD + lane * 4;
            float4 xv = *(const float4*)(X + off);
            float4 tv;
            tv.x = v.x + bz.x + xv.x; tv.y = v.y + bz.y + xv.y;
            tv.z = v.z + bz.z + xv.z; tv.w = v.w + bz.w + xv.w;
            float s  = tv.x + tv.y + tv.z + tv.w;
            float s2 = tv.x*tv.x + tv.y*tv.y + tv.z*tv.z + tv.w*tv.w;
#pragma unroll
            for (int o = 16; o > 0; o >>= 1) {
                s  += __shfl_xor_sync(0xffffffffu, s,  o);
                s2 += __shfl_xor_sync(0xffffffffu, s2, o);
            }
            float mean = s * (1.f / DD);
            float var  = s2 * (1.f / DD) - mean * mean;
            float rstd = rsqrtf(var + 1e-5f);
            float4 y;
            y.x = (tv.x - mean) * rstd * gv.x + bv.x;
            y.y = (tv.y - mean) * rstd * gv.y + bv.y;
            y.z = (tv.z - mean) * rstd * gv.z + bv.z;
            y.w = (tv.w - mean) * rstd * gv.w + bv.w;
            *(float4*)(X + off) = y;
            __half2 h0 = __floats2half2_rn(y.x, y.y);
            __half2 h1 = __floats2half2_rn(y.z, y.w);
            uint2 u;
            u.x = *reinterpret_cast<uint32_t*>(&h0);
            u.y = *reinterpret_cast<uint32_t*>(&h1);
            *(uint2*)(Xh + off) = u;
        }
    } else {
        // bias (+ReLU), fp16 out: 4096 float4 reads, 16/thread
#pragma unroll
        for (int i = 0; i < 16; i++) {
            int idx = i * 256 + tid;
            int row = idx >> 5;
            int cc  = (idx & 31) * 4;
            float4 v  = *(float4*)(smf + row * CLD + cc);
            float4 bz = *(const float4*)(bias + bn + cc);
            v.x += bz.x; v.y += bz.y; v.z += bz.z; v.w += bz.w;
            if (mode == 1) {
                v.x = fmaxf(v.x, 0.f); v.y = fmaxf(v.y, 0.f);
                v.z = fmaxf(v.z, 0.f); v.w = fmaxf(v.w, 0.f);
            }
            __half2 h0 = __floats2half2_rn(v.x, v.y);
            __half2 h1 = __floats2half2_rn(v.z, v.w);
            uint2 u;
            u.x = *reinterpret_cast<uint32_t*>(&h0);
            u.y = *reinterpret_cast<uint32_t*>(&h1);
            *(uint2*)(Ch + (bm + row) * N + bn + cc) = u;
        }
    }
}

// ---------------------------------------------------------------------------
// Fast exp (FFMA-only)
// ---------------------------------------------------------------------------
__device__ __forceinline__ float fast_exp(float x) {
    x = fmaxf(x, -80.f);
    float t  = x * 1.4426950408889634f;
    float fn = t + 12582912.f;
    int   ni = __float_as_int(fn) - 0x4B400000;
    float r  = t - (fn - 12582912.f);
    float p  = 0.00133336f;
    p = fmaf(p, r, 0.00961813f);
    p = fmaf(p, r, 0.05550411f);
    p = fmaf(p, r, 0.24022651f);
    p = fmaf(p, r, 0.69314718f);
    p = fmaf(p, r, 1.0f);
    return p * __int_as_float((ni + 127) << 23);
}

// ---------------------------------------------------------------------------
// Attention: fp16 qkv in, fp16 out; fp32 math. One block per (b,h).
// ---------------------------------------------------------------------------
__global__ __launch_bounds__(128) void attn_kernel(
    const __half* __restrict__ qkv, const float* __restrict__ mask,
    __half* __restrict__ out)
{
    const int h = blockIdx.x;
    const int b = blockIdx.y;
    const int t = threadIdx.x;

    __shared__ float ks[TT][HDIM];
    __shared__ float vs[TT][HDIM];
    __shared__ float ms[TT];

    const __half* base = qkv + (size_t)b * TT * 3 * DD;
    {
        const __half* kr = base + (size_t)t * 3 * DD + DD + h * HDIM;
        const __half* vr = kr + DD;
#pragma unroll
        for (int c = 0; c < 2; c++) {
            uint4 rk = ((const uint4*)kr)[c];
            uint4 rv = ((const uint4*)vr)[c];
            const uint32_t* pk = &rk.x;
            const uint32_t* pv = &rv.x;
#pragma unroll
            for (int j = 0; j < 4; j++) {
                float2 fk = __half22float2(*(const __half2*)&pk[j]);
                float2 fv = __half22float2(*(const __half2*)&pv[j]);
                ks[t][c * 8 + j * 2]     = fk.x;
                ks[t][c * 8 + j * 2 + 1] = fk.y;
                vs[t][c * 8 + j * 2]     = fv.x;
                vs[t][c * 8 + j * 2 + 1] = fv.y;
            }
        }
        ms[t] = mask[b * TT + t];
    }
    __syncthreads();

    float q[HDIM];
    {
        const __half* qr = base + (size_t)t * 3 * DD + h * HDIM;
#pragma unroll
        for (int c = 0; c < 2; c++) {
            uint4 rq = ((const uint4*)qr)[c];
            const uint32_t* pq = &rq.x;
#pragma unroll
            for (int j = 0; j < 4; j++) {
                float2 fq = __half22float2(*(const __half2*)&pq[j]);
                q[c * 8 + j * 2]     = fq.x;
                q[c * 8 + j * 2 + 1] = fq.y;
            }
        }
    }

    const float scale = 0.25f;
    float s = 0.f;
    float o[HDIM];
#pragma unroll
    for (int c = 0; c < HDIM; c++) o[c] = 0.f;

    for (int j = 0; j < TT; j++) {
        float d = 0.f;
#pragma unroll
        for (int c = 0; c < HDIM; c++) d = fmaf(q[c], ks[j][c], d);
        float p = fast_exp(fmaf(d, scale, ms[j]));
        s += p;
#pragma unroll
        for (int c = 0; c < HDIM; c++) o[c] = fmaf(p, vs[j][c], o[c]);
    }
    float inv = 1.f / s;
    __half* op = out + (size_t)(b * TT + t) * DD + h * HDIM;
    uint4 w[2];
#pragma unroll
    for (int c = 0; c < 2; c++) {
        uint32_t* pw = &w[c].x;
#pragma unroll
        for (int j = 0; j < 4; j++) {
            __half2 hv = __floats2half2_rn(o[c * 8 + j * 2] * inv,
                                           o[c * 8 + j * 2 + 1] * inv);
            pw[j] = *reinterpret_cast<uint32_t*>(&hv);
        }
        ((uint4*)op)[c] = w[c];
    }
}

// ---------------------------------------------------------------------------
extern "C" void kernel_launch(void* const* d_in, const int* in_sizes, int n_in,
                              void* d_out, int out_size)
{
    const float* x_in      = (const float*)d_in[0];
    const float* mask      = (const float*)d_in[1];
    const float* in_proj_w = (const float*)d_in[2];
    const float* in_proj_b = (const float*)d_in[3];
    const float* out_w     = (const float*)d_in[4];
    const float* out_b     = (const float*)d_in[5];
    const float* ln1_g     = (const float*)d_in[6];
    const float* ln1_b     = (const float*)d_in[7];
    const float* ff1_w     = (const float*)d_in[8];
    const float* ff1_b     = (const float*)d_in[9];
    const float* ff2_w     = (const float*)d_in[10];
    const float* ff2_b     = (const float*)d_in[11];
    const float* ln2_g     = (const float*)d_in[12];
    const float* ln2_b     = (const float*)d_in[13];
    float* x = (float*)d_out;

    __half *wqkv, *wout, *wff1, *wff2, *xh, *qkvh, *attnh, *hh;
    cudaGetSymbolAddress((void**)&wqkv, g_wqkv);
    cudaGetSymbolAddress((void**)&wout, g_wout);
    cudaGetSymbolAddress((void**)&wff1, g_wff1);
    cudaGetSymbolAddress((void**)&wff2, g_wff2);
    cudaGetSymbolAddress((void**)&xh,   g_xh);
    cudaGetSymbolAddress((void**)&qkvh, g_qkvh);
    cudaGetSymbolAddress((void**)&attnh,g_attnh);
    cudaGetSymbolAddress((void**)&hh,   g_hh);

    cudaFuncSetAttribute(gemm_h, cudaFuncAttributeMaxDynamicSharedMemorySize, SMEM_DYN);

    // fp32 residual stream := input
    cudaMemcpyAsync(x, x_in, sizeof(float) * (size_t)MM * DD,
                    cudaMemcpyDeviceToDevice);
    // weight + input conversions to fp16
    {
        int n;
        n = NL * 3 * DD * DD / 4; cvt_f2h<<<(n + 255) / 256, 256>>>(in_proj_w, wqkv, n);
        n = NL * DD * DD / 4;     cvt_f2h<<<(n + 255) / 256, 256>>>(out_w,  wout, n);
        n = NL * FFD * DD / 4;    cvt_f2h<<<(n + 255) / 256, 256>>>(ff1_w,  wff1, n);
        n = NL * DD * FFD / 4;    cvt_f2h<<<(n + 255) / 256, 256>>>(ff2_w,  wff2, n);
        n = MM * DD / 4;          cvt_f2h<<<(n + 255) / 256, 256>>>(x_in,   xh,   n);
    }

    for (int l = 0; l < NL; l++) {
        // qkv = x @ Wqkv^T + b   [MM, 384] fp16
        gemm_h<<<dim3(3, MM / 128), 256, SMEM_DYN>>>(
            xh, wqkv + (size_t)l * 3 * DD * DD, in_proj_b + (size_t)l * 3 * DD,
            qkvh, nullptr, nullptr, nullptr, nullptr, 3 * DD, DD, 0);
        // attention -> attnh [MM, DD] fp16
        attn_kernel<<<dim3(HH, BB), 128>>>(qkvh, mask, attnh);
        // x = LN(x + attnh @ out_w^T + out_b); xh mirror
        gemm_h<<<dim3(1, MM / 128), 256, SMEM_DYN>>>(
            attnh, wout + (size_t)l * DD * DD, out_b + (size_t)l * DD,
            nullptr, x, xh, ln1_g + (size_t)l * DD, ln1_b + (size_t)l * DD, DD, DD, 2);
        // h = relu(x @ ff1_w^T + b) -> hh [MM, FFD] fp16
        gemm_h<<<dim3(4, MM / 128), 256, SMEM_DYN>>>(
            xh, wff1 + (size_t)l * FFD * DD, ff1_b + (size_t)l * FFD,
            hh, nullptr, nullptr, nullptr, nullptr, FFD, DD, 1);
        // x = LN(x + hh @ ff2_w^T + b); xh mirror
        gemm_h<<<dim3(1, MM / 128), 256, SMEM_DYN>>>(
            hh, wff2 + (size_t)l * DD * FFD, ff2_b + (size_t)l * DD,
            nullptr, x, xh, ln2_g + (size_t)l * DD, ln2_b + (size_t)l * DD, DD, FFD, 2);
    }
}